// round 1
// baseline (speedup 1.0000x reference)
#include <cuda_runtime.h>

// FourierKANAdapter: out[t,d] = x[t,d] + c0[d] + sum_{k=1..3} sin(k*x)*cs[d,k] + cos(k*x)*cc[d,k]
// T=32768, DIM=1024, K=3. coeffs layout: [DIM][7] = {c0, cs1, cc1, cs2, cc2, cs3, cc3}
//
// Strategy: memory-bound elementwise. Each thread owns 4 consecutive d-columns,
// keeps its 28 coefficients in registers, and grid-strides over rows with
// float4 loads/stores (warp = 128 consecutive floats -> fully coalesced).

#define KAN_T   32768
#define KAN_DIM 1024

__global__ __launch_bounds__(256, 4)
void fourier_kan_kernel(const float* __restrict__ x,
                        const float* __restrict__ coeffs,
                        float* __restrict__ out)
{
    // Each thread handles d_base .. d_base+3 (one float4 lane across DIM).
    const int d_base = threadIdx.x * 4;   // blockDim.x == 256 -> covers DIM=1024

    // Load 7 coefficients for each of the 4 owned columns into registers.
    float c0[4], cs1[4], cc1[4], cs2[4], cc2[4], cs3[4], cc3[4];
#pragma unroll
    for (int j = 0; j < 4; j++) {
        const float* cp = coeffs + (d_base + j) * 7;
        c0[j]  = __ldg(cp + 0);
        cs1[j] = __ldg(cp + 1);
        cc1[j] = __ldg(cp + 2);
        cs2[j] = __ldg(cp + 3);
        cc2[j] = __ldg(cp + 4);
        cs3[j] = __ldg(cp + 5);
        cc3[j] = __ldg(cp + 6);
    }

    // Grid-stride over rows. Process 2 rows per iteration for extra MLP.
    for (int t = blockIdx.x * 2; t < KAN_T; t += gridDim.x * 2) {
        const float4* xin0 = reinterpret_cast<const float4*>(x + (size_t)t * KAN_DIM + d_base);
        float4 xv0 = __ldg(xin0);

        bool have1 = (t + 1) < KAN_T;
        float4 xv1 = make_float4(0.f, 0.f, 0.f, 0.f);
        if (have1) {
            const float4* xin1 = reinterpret_cast<const float4*>(x + (size_t)(t + 1) * KAN_DIM + d_base);
            xv1 = __ldg(xin1);
        }

        float4 ov0, ov1;
        float* xi0 = reinterpret_cast<float*>(&xv0);
        float* xi1 = reinterpret_cast<float*>(&xv1);
        float* oo0 = reinterpret_cast<float*>(&ov0);
        float* oo1 = reinterpret_cast<float*>(&ov1);

#pragma unroll
        for (int j = 0; j < 4; j++) {
            // row t
            {
                float xe = xi0[j];
                float s1, c1;
                __sincosf(xe, &s1, &c1);
                float s2 = 2.0f * s1 * c1;
                float c2 = fmaf(2.0f * c1, c1, -1.0f);
                float s3 = fmaf(s1, c2, c1 * s2);
                float c3 = fmaf(c1, c2, -s1 * s2);
                float r = fmaf(s1, cs1[j], c0[j]);
                r = fmaf(c1, cc1[j], r);
                r = fmaf(s2, cs2[j], r);
                r = fmaf(c2, cc2[j], r);
                r = fmaf(s3, cs3[j], r);
                r = fmaf(c3, cc3[j], r);
                oo0[j] = xe + r;
            }
            // row t+1
            {
                float xe = xi1[j];
                float s1, c1;
                __sincosf(xe, &s1, &c1);
                float s2 = 2.0f * s1 * c1;
                float c2 = fmaf(2.0f * c1, c1, -1.0f);
                float s3 = fmaf(s1, c2, c1 * s2);
                float c3 = fmaf(c1, c2, -s1 * s2);
                float r = fmaf(s1, cs1[j], c0[j]);
                r = fmaf(c1, cc1[j], r);
                r = fmaf(s2, cs2[j], r);
                r = fmaf(c2, cc2[j], r);
                r = fmaf(s3, cs3[j], r);
                r = fmaf(c3, cc3[j], r);
                oo1[j] = xe + r;
            }
        }

        *reinterpret_cast<float4*>(out + (size_t)t * KAN_DIM + d_base) = ov0;
        if (have1) {
            *reinterpret_cast<float4*>(out + (size_t)(t + 1) * KAN_DIM + d_base) = ov1;
        }
    }
}

extern "C" void kernel_launch(void* const* d_in, const int* in_sizes, int n_in,
                              void* d_out, int out_size)
{
    const float* x      = (const float*)d_in[0];
    const float* coeffs = (const float*)d_in[1];
    float*       out    = (float*)d_out;

    // 256 threads/block = one full DIM row per block-iteration.
    // 2 rows per loop iter -> grid covers T/2 row-pairs; pick a grid that
    // keeps all 148+ SMs busy with several CTAs each.
    dim3 block(256);
    dim3 grid(2048);   // 32768 rows / 2 rows-per-iter / 2048 blocks = 8 iters/block
    fourier_kan_kernel<<<grid, block>>>(x, coeffs, out);
}

// round 2
// speedup vs baseline: 1.0091x; 1.0091x over previous
#include <cuda_runtime.h>

// FourierKANAdapter: out[t,d] = x[t,d] + c0[d] + sum_{k=1..3} sin(kx)*cs[d,k] + cos(kx)*cc[d,k]
// T=32768, DIM=1024, K=3. coeffs layout: [DIM][7] = {c0, cs1, cc1, cs2, cc2, cs3, cc3}
//
// R2 strategy: HBM-bound; raise loads-in-flight.
//  - 512 threads/block, each thread owns 2 d-columns (14 coeff regs, not 28)
//  - 4 rows per iteration, loads front-batched (MLP_p1 = 4)
//  - software pipeline: next iteration's 4 loads issued before computing current
//  - no predication: grid/trip counts divide exactly (1024 blocks x 4 rows x 8 iters = 32768)

#define KAN_T    32768
#define KAN_DIM  1024
#define ROWS_PER_ITER 4
#define GRID_BLOCKS   1024
#define N_ITERS  (KAN_T / (GRID_BLOCKS * ROWS_PER_ITER))   // 8
#define ROW_STRIDE (GRID_BLOCKS * ROWS_PER_ITER)           // 4096

__global__ __launch_bounds__(512)
void fourier_kan_kernel(const float* __restrict__ x,
                        const float* __restrict__ coeffs,
                        float* __restrict__ out)
{
    const int d = threadIdx.x * 2;   // 512 threads x float2 = 1024 = DIM

    // 7 coefficients for each of the 2 owned columns -> 14 registers.
    float c0[2], cs1[2], cc1[2], cs2[2], cc2[2], cs3[2], cc3[2];
#pragma unroll
    for (int j = 0; j < 2; j++) {
        const float* cp = coeffs + (d + j) * 7;
        c0[j]  = __ldg(cp + 0);
        cs1[j] = __ldg(cp + 1);
        cc1[j] = __ldg(cp + 2);
        cs2[j] = __ldg(cp + 3);
        cc2[j] = __ldg(cp + 4);
        cs3[j] = __ldg(cp + 5);
        cc3[j] = __ldg(cp + 6);
    }

    const int t0 = blockIdx.x * ROWS_PER_ITER;

    // Prologue: load first 4 rows.
    float2 cur[ROWS_PER_ITER];
#pragma unroll
    for (int r = 0; r < ROWS_PER_ITER; r++) {
        cur[r] = __ldcs(reinterpret_cast<const float2*>(
            x + (size_t)(t0 + r) * KAN_DIM + d));
    }

    for (int it = 0; it < N_ITERS; it++) {
        const int t = t0 + it * ROW_STRIDE;

        // Prefetch next iteration's rows (clamped on last iter -> cheap L2 re-hit).
        const int tn = (it + 1 < N_ITERS) ? (t + ROW_STRIDE) : t;
        float2 nxt[ROWS_PER_ITER];
#pragma unroll
        for (int r = 0; r < ROWS_PER_ITER; r++) {
            nxt[r] = __ldcs(reinterpret_cast<const float2*>(
                x + (size_t)(tn + r) * KAN_DIM + d));
        }

        // Compute + store current 4 rows.
#pragma unroll
        for (int r = 0; r < ROWS_PER_ITER; r++) {
            float xe[2] = {cur[r].x, cur[r].y};
            float oe[2];
#pragma unroll
            for (int j = 0; j < 2; j++) {
                float s1, c1;
                __sincosf(xe[j], &s1, &c1);
                float s2 = 2.0f * s1 * c1;
                float c2 = fmaf(2.0f * c1, c1, -1.0f);
                float s3 = fmaf(s1, c2, c1 * s2);
                float c3 = fmaf(c1, c2, -s1 * s2);
                float rr = fmaf(s1, cs1[j], c0[j]);
                rr = fmaf(c1, cc1[j], rr);
                rr = fmaf(s2, cs2[j], rr);
                rr = fmaf(c2, cc2[j], rr);
                rr = fmaf(s3, cs3[j], rr);
                rr = fmaf(c3, cc3[j], rr);
                oe[j] = xe[j] + rr;
            }
            *reinterpret_cast<float2*>(out + (size_t)(t + r) * KAN_DIM + d) =
                make_float2(oe[0], oe[1]);
        }

#pragma unroll
        for (int r = 0; r < ROWS_PER_ITER; r++) cur[r] = nxt[r];
    }
}

extern "C" void kernel_launch(void* const* d_in, const int* in_sizes, int n_in,
                              void* d_out, int out_size)
{
    const float* x      = (const float*)d_in[0];
    const float* coeffs = (const float*)d_in[1];
    float*       out    = (float*)d_out;

    fourier_kan_kernel<<<GRID_BLOCKS, 512>>>(x, coeffs, out);
}

// round 4
// speedup vs baseline: 1.1211x; 1.1110x over previous
#include <cuda_runtime.h>

// FourierKANAdapter: out[t,d] = x[t,d] + c0[d] + sum_{k=1..3} sin(kx)*cs[d,k] + cos(kx)*cc[d,k]
// T=32768, DIM=1024, K=3. coeffs layout: [DIM][7] = {c0, cs1, cc1, cs2, cc2, cs3, cc3}
//
// R3 strategy: latency/occupancy-bound fix.
//  - ONE column per thread -> only 7 coefficient registers.
//  - blockDim=512, block covers half of DIM (bid&1 selects half); occupancy
//    quantizes in 512-thread steps. __launch_bounds__(512,3) caps regs at 42.
//  - 16 rows per block: 4 iterations x 4 rows, software-pipelined scalar loads.
//  - scalar 4B loads/stores are fully coalesced (warp = 128 contiguous bytes).

#define KAN_T    32768
#define KAN_DIM  1024
#define ROWS_PER_BLOCK 16
#define ROWS_PER_ITER  4
#define N_ITERS  (ROWS_PER_BLOCK / ROWS_PER_ITER)          // 4
#define GRID_BLOCKS ((KAN_T / ROWS_PER_BLOCK) * 2)         // 4096

__global__ __launch_bounds__(512, 3)
void fourier_kan_kernel(const float* __restrict__ x,
                        const float* __restrict__ coeffs,
                        float* __restrict__ out)
{
    const int d  = ((blockIdx.x & 1) << 9) + threadIdx.x;   // column owned by this thread
    const int t0 = (blockIdx.x >> 1) * ROWS_PER_BLOCK;      // first row of this block

    // 7 coefficients for the single owned column.
    const float* cp = coeffs + d * 7;
    const float c0  = __ldg(cp + 0);
    const float cs1 = __ldg(cp + 1);
    const float cc1 = __ldg(cp + 2);
    const float cs2 = __ldg(cp + 3);
    const float cc2 = __ldg(cp + 4);
    const float cs3 = __ldg(cp + 5);
    const float cc3 = __ldg(cp + 6);

    const float* __restrict__ xp = x   + (size_t)t0 * KAN_DIM + d;
    float*       __restrict__ op = out + (size_t)t0 * KAN_DIM + d;

    // Prologue: first 4 rows.
    float cur[ROWS_PER_ITER];
#pragma unroll
    for (int r = 0; r < ROWS_PER_ITER; r++)
        cur[r] = __ldcs(xp + r * KAN_DIM);

#pragma unroll
    for (int it = 0; it < N_ITERS; it++) {
        // Prefetch next 4 rows (clamped on the last iteration -> L1/L2 re-hit).
        const int pbase = (it + 1 < N_ITERS) ? (it + 1) * ROWS_PER_ITER
                                             : it * ROWS_PER_ITER;
        float nxt[ROWS_PER_ITER];
#pragma unroll
        for (int r = 0; r < ROWS_PER_ITER; r++)
            nxt[r] = __ldcs(xp + (pbase + r) * KAN_DIM);

        // Compute + store current 4 rows.
#pragma unroll
        for (int r = 0; r < ROWS_PER_ITER; r++) {
            const float xe = cur[r];
            float s1, c1;
            __sincosf(xe, &s1, &c1);
            const float s2 = 2.0f * s1 * c1;
            const float c2 = fmaf(2.0f * c1, c1, -1.0f);
            const float s3 = fmaf(s1, c2, c1 * s2);
            const float c3 = fmaf(c1, c2, -s1 * s2);
            float rr = fmaf(s1, cs1, c0);
            rr = fmaf(c1, cc1, rr);
            rr = fmaf(s2, cs2, rr);
            rr = fmaf(c2, cc2, rr);
            rr = fmaf(s3, cs3, rr);
            rr = fmaf(c3, cc3, rr);
            __stcs(op + (it * ROWS_PER_ITER + r) * KAN_DIM, xe + rr);
        }

#pragma unroll
        for (int r = 0; r < ROWS_PER_ITER; r++) cur[r] = nxt[r];
    }
}

extern "C" void kernel_launch(void* const* d_in, const int* in_sizes, int n_in,
                              void* d_out, int out_size)
{
    const float* x      = (const float*)d_in[0];
    const float* coeffs = (const float*)d_in[1];
    float*       out    = (float*)d_out;

    fourier_kan_kernel<<<GRID_BLOCKS, 512>>>(x, coeffs, out);
}